// round 6
// baseline (speedup 1.0000x reference)
#include <cuda_runtime.h>

// HyperPatch: b=16, c=8, h=w=512, fh=fw=16, c_out=8, sc=64, K=3, PAD=1
// R6: conv = pixel-pairs-in-lanes f32x2 with OVERLAPPING odd accumulators for
//     the kc=1 tap -> inner loop is pure LDS + FFMA2 (no per-iter packing).
//     Weights pre-duplicated (w,w) in smem. 512 thr/CTA, 2co x 8px/thread.
//     kernel1 = thin-CTA tiled GEMM, o-chunk 32, f32x2.

#define N_TILES 4096
__device__ float g_wpp[N_TILES * 576];   // scratch: [n][o]

// ---- f32x2 helpers ---------------------------------------------------------
__device__ __forceinline__ unsigned long long ffma2(
    unsigned long long a, unsigned long long b, unsigned long long c)
{
    unsigned long long d;
    asm("fma.rn.f32x2 %0, %1, %2, %3;" : "=l"(d) : "l"(a), "l"(b), "l"(c));
    return d;
}
__device__ __forceinline__ unsigned long long pack2(float x)
{
    unsigned long long d;
    asm("mov.b64 %0, {%1, %1};" : "=l"(d) : "f"(x));
    return d;
}
__device__ __forceinline__ float lo2(unsigned long long v)
{
    float a, b;
    asm("mov.b64 {%0, %1}, %2;" : "=f"(a), "=f"(b) : "l"(v));
    return a;
}
__device__ __forceinline__ float hi2(unsigned long long v)
{
    float a, b;
    asm("mov.b64 {%0, %1}, %2;" : "=f"(a), "=f"(b) : "l"(v));
    return b;
}

// ---------------------------------------------------------------------------
// Kernel 1: g_wpp[4096 x 576] = S[4096 x 64] @ w_s2w^T
// grid (32, 18), 128 threads. CTA: 128 n x 32 o. Thread: 1 n x 32 o.
// ---------------------------------------------------------------------------
__global__ __launch_bounds__(128) void hyper_weights_kernel(
    const float* __restrict__ w_s2w,   // [576][64]
    const float* __restrict__ s_in)    // [16][64][256]
{
    __shared__ __align__(16) float wsm[64][36];   // [s][o], pad 36 (16B align/row)

    const int t  = threadIdx.x;
    const int n0 = blockIdx.x * 128;
    const int o0 = blockIdx.y * 32;
    const int b  = n0 >> 8;
    const int f0 = n0 & 255;

    // stage 32 o-rows of w_s2w, coalesced read, transpose into wsm[s][o]
#pragma unroll
    for (int i = t; i < 2048; i += 128) {
        int o = i >> 6;
        int s = i & 63;
        wsm[s][o] = w_s2w[(size_t)(o0 + o) * 64 + s];
    }
    __syncthreads();

    const float* sp = s_in + b * 16384 + f0 + t;

    unsigned long long acc[16];
#pragma unroll
    for (int k = 0; k < 16; k++) acc[k] = 0ull;

#pragma unroll 4
    for (int s = 0; s < 64; s++) {
        unsigned long long a2 = pack2(__ldg(sp + s * 256));
        const ulonglong2* wp = reinterpret_cast<const ulonglong2*>(&wsm[s][0]);
#pragma unroll
        for (int j = 0; j < 4; j++) {
            ulonglong2 w = wp[j];                 // o-pairs (4j,4j+1),(4j+2,4j+3)
            acc[4 * j]     = ffma2(a2, w.x, acc[4 * j]);
            acc[4 * j + 1] = ffma2(a2, w.y, acc[4 * j + 1]);
        }
        // second halves interleaved for ILP
#pragma unroll
        for (int j = 0; j < 4; j++) {
            ulonglong2 w = wp[j];
            (void)w;
        }
        // note: 16 o-pairs total = 8 ulonglong2 reads
        const ulonglong2* wq = wp + 4;
#pragma unroll
        for (int j = 0; j < 4; j++) {
            ulonglong2 w = wq[j];
            acc[4 * j + 2] = ffma2(a2, w.x, acc[4 * j + 2]);
            acc[4 * j + 3] = ffma2(a2, w.y, acc[4 * j + 3]);
        }
    }

    // acc index k corresponds to o-pair: k in [0,1]: o (0,1),(2,3); pattern:
    // j loop above: acc[4j+0]=pair(4j*2? ) -- fix mapping by storing per slot:
    // wp[j] covers o (8j..8j+3)? No: wp is ulonglong2 over [s][0..31]:
    // wp[j].x = o-pair(4j, 4j+1)?? Actually ulonglong2 j covers floats 4j..4j+3,
    // i.e. o-pairs (4j,4j+1) and (4j+2,4j+3). wq[j] covers floats 16+4j..19+4j.
    float* dst = g_wpp + (size_t)(n0 + t) * 576 + o0;
    // store in matching order: acc[4j]   -> o 4j..4j+1
    //                          acc[4j+1] -> o 4j+2..4j+3
    //                          acc[4j+2] -> o 16+4j..17+4j
    //                          acc[4j+3] -> o 18+4j..19+4j
#pragma unroll
    for (int j = 0; j < 4; j++) {
        *reinterpret_cast<unsigned long long*>(dst + 4 * j)      = acc[4 * j];
        *reinterpret_cast<unsigned long long*>(dst + 4 * j + 2)  = acc[4 * j + 1];
        *reinterpret_cast<unsigned long long*>(dst + 16 + 4 * j)     = acc[4 * j + 2];
        *reinterpret_cast<unsigned long long*>(dst + 16 + 4 * j + 2) = acc[4 * j + 3];
    }
}

// ---------------------------------------------------------------------------
// Kernel 2: per-tile 3x3 conv. grid = 4096 tiles, 512 threads.
// Thread: 2 c_out (quarter coq = t>>7) x 8 px, f32x2 over PIXEL pairs.
//   accE[c][p] = output pair (2p, 2p+1), taps kc=0 (input P[p]) and kc=2 (P[p+1])
//   accO[c][q] = output pair (2q-1, 2q), tap kc=1 (input P[q])  -- overlapping
// All input operands aligned LDS.128 pairs; weights (w,w)-duplicated in smem.
// ---------------------------------------------------------------------------
__global__ __launch_bounds__(512, 2) void hyper_conv_kernel(
    const float* __restrict__ x,       // [16][8][512][512]
    float* __restrict__ out)           // [16][8][512][512]
{
    __shared__ float sin_s[8][34][36];                         // 38.25 KB
    __shared__ __align__(16) unsigned long long wsm2[72][8];   // dup (w,w), 4.5 KB

    const int n  = blockIdx.x;
    const int t  = threadIdx.x;
    const int b  = n >> 8;
    const int fy = (n >> 4) & 15;
    const int fx = n & 15;

    // stage weights duplicated: g_wpp[n][co*72 + kidx] -> wsm2[kidx][co] = (v,v)
    const float* wpp_n = g_wpp + (size_t)n * 576;
    for (int i = t; i < 576; i += 512) {
        int co   = i / 72;
        int kidx = i - co * 72;
        float v  = wpp_n[i];
        *reinterpret_cast<float2*>(&wsm2[kidx][co]) = make_float2(v, v);
    }

    // stage 34x34x8 reflect-padded input window
    const float* xb  = x + (size_t)b * (8 * 512 * 512);
    const int row0 = fy * 32 - 1;
    const int col0 = fx * 32 - 1;
    for (int i = t; i < 8 * 34 * 34; i += 512) {
        int ci  = i / 1156;
        int rem = i - ci * 1156;
        int r   = rem / 34;
        int cl  = rem - r * 34;
        int gr = row0 + r;  gr = gr < 0 ? -gr : (gr > 511 ? 1022 - gr : gr);
        int gc = col0 + cl; gc = gc < 0 ? -gc : (gc > 511 ? 1022 - gc : gc);
        sin_s[ci][r][cl] = xb[(ci << 18) + (gr << 9) + gc];
    }
    __syncthreads();

    const int coq = t >> 7;             // 0..3 -> c_out pair base 2*coq
    const int tt  = t & 127;
    const int py  = tt >> 2;            // 0..31
    const int px0 = (tt & 3) << 3;      // 0,8,16,24

    unsigned long long accE[2][4];      // [c][p] -> outputs (2p, 2p+1)
    unsigned long long accO[2][5];      // [c][q] -> outputs (2q-1, 2q)
#pragma unroll
    for (int c = 0; c < 2; c++) {
#pragma unroll
        for (int p = 0; p < 4; p++) accE[c][p] = 0ull;
#pragma unroll
        for (int q = 0; q < 5; q++) accO[c][q] = 0ull;
    }

#pragma unroll 1
    for (int ci = 0; ci < 8; ci++) {
#pragma unroll
        for (int kr = 0; kr < 3; kr++) {
            const float* rowp = &sin_s[ci][py + kr][px0];
            ulonglong2 U01 = *reinterpret_cast<const ulonglong2*>(rowp);     // P0,P1
            ulonglong2 U23 = *reinterpret_cast<const ulonglong2*>(rowp + 4); // P2,P3
            unsigned long long P4 =
                *reinterpret_cast<const unsigned long long*>(rowp + 8);
            unsigned long long P[5] = {U01.x, U01.y, U23.x, U23.y, P4};

            const int kbase = ci * 9 + kr * 3;
            ulonglong2 w0 = *reinterpret_cast<const ulonglong2*>(&wsm2[kbase][2 * coq]);
            ulonglong2 w1 = *reinterpret_cast<const ulonglong2*>(&wsm2[kbase + 1][2 * coq]);
            ulonglong2 w2 = *reinterpret_cast<const ulonglong2*>(&wsm2[kbase + 2][2 * coq]);

#pragma unroll
            for (int p = 0; p < 4; p++) {
                accE[0][p] = ffma2(w0.x, P[p], accE[0][p]);
                accE[1][p] = ffma2(w0.y, P[p], accE[1][p]);
                accE[0][p] = ffma2(w2.x, P[p + 1], accE[0][p]);
                accE[1][p] = ffma2(w2.y, P[p + 1], accE[1][p]);
            }
#pragma unroll
            for (int q = 0; q < 5; q++) {
                accO[0][q] = ffma2(w1.x, P[q], accO[0][q]);
                accO[1][q] = ffma2(w1.y, P[q], accO[1][q]);
            }
        }
    }

    const int gy = (fy << 5) + py;
    const int gx = (fx << 5) + px0;
#pragma unroll
    for (int c = 0; c < 2; c++) {
        float o[8];
#pragma unroll
        for (int p = 0; p < 4; p++) {
            o[2 * p]     = lo2(accE[c][p]) + hi2(accO[c][p]);
            o[2 * p + 1] = hi2(accE[c][p]) + lo2(accO[c][p + 1]);
        }
        const int co = 2 * coq + c;
        float* op = out + (((size_t)(b * 8 + co)) << 18) + (gy << 9) + gx;
        *reinterpret_cast<float4*>(op)     = make_float4(o[0], o[1], o[2], o[3]);
        *reinterpret_cast<float4*>(op + 4) = make_float4(o[4], o[5], o[6], o[7]);
    }
}

// ---------------------------------------------------------------------------
extern "C" void kernel_launch(void* const* d_in, const int* in_sizes, int n_in,
                              void* d_out, int out_size)
{
    (void)in_sizes; (void)n_in; (void)out_size;
    const float* x     = (const float*)d_in[0];   // [16,8,512,512]
    const float* s     = (const float*)d_in[1];   // [16,64,16,16]
    const float* w_s2w = (const float*)d_in[2];   // [576,64]
    float* out = (float*)d_out;                   // [16,8,512,512]

    hyper_weights_kernel<<<dim3(32, 18), 128>>>(w_s2w, s);
    hyper_conv_kernel<<<N_TILES, 512>>>(x, out);
}

// round 7
// speedup vs baseline: 1.2756x; 1.2756x over previous
#include <cuda_runtime.h>

// HyperPatch: b=16, c=8, h=w=512, fh=fw=16, c_out=8, sc=64, K=3, PAD=1
// R7: conv inner loop = pure LDS + FFMA2.
//   - inputs pre-duplicated (v,v) u64 pairs in smem; two ci-passes (4+4)
//   - weights plain f32 [kidx][co] -> LDS.128 broadcast gives (co,co+1) f32x2
//   - row stride 36 u64 + 2-u64 gap after col 16 -> conflict-free LDS.128

#define N_TILES 4096
__device__ float g_wpp[N_TILES * 576];   // scratch: [n][o]

// ---- f32x2 helpers ---------------------------------------------------------
__device__ __forceinline__ unsigned long long ffma2(
    unsigned long long a, unsigned long long b, unsigned long long c)
{
    unsigned long long d;
    asm("fma.rn.f32x2 %0, %1, %2, %3;" : "=l"(d) : "l"(a), "l"(b), "l"(c));
    return d;
}
__device__ __forceinline__ void unpack2(unsigned long long v, float& lo, float& hi)
{
    asm("mov.b64 {%0, %1}, %2;" : "=f"(lo), "=f"(hi) : "l"(v));
}

// ---------------------------------------------------------------------------
// Kernel 1: g_wpp[4096 x 576] = S[4096 x 64] @ w_s2w^T   (proven R1 version)
// ---------------------------------------------------------------------------
__global__ __launch_bounds__(128) void hyper_weights_kernel(
    const float* __restrict__ w_s2w,   // [576][64]
    const float* __restrict__ s_in)    // [16][64][256]
{
    __shared__ float wsm[512];   // 8 rows x 64
    const int t  = threadIdx.x;
    const int o0 = blockIdx.y * 8;

#pragma unroll
    for (int i = 0; i < 4; i++)
        wsm[t + i * 128] = w_s2w[o0 * 64 + t + i * 128];
    __syncthreads();

    const int n    = blockIdx.x * 128 + t;
    const int b    = n >> 8;
    const int fyfx = n & 255;
    const float* sp = s_in + b * (64 * 256) + fyfx;

    float acc[8];
#pragma unroll
    for (int k = 0; k < 8; k++) acc[k] = 0.f;

#pragma unroll 8
    for (int s = 0; s < 64; s++) {
        float a = __ldg(sp + s * 256);
#pragma unroll
        for (int k = 0; k < 8; k++)
            acc[k] = fmaf(wsm[k * 64 + s], a, acc[k]);
    }

    float4* dst = reinterpret_cast<float4*>(g_wpp + (size_t)n * 576 + o0);
    dst[0] = make_float4(acc[0], acc[1], acc[2], acc[3]);
    dst[1] = make_float4(acc[4], acc[5], acc[6], acc[7]);
}

// ---------------------------------------------------------------------------
// Kernel 2: per-tile 3x3 conv. grid = 4096, 256 threads.
// Thread: 4 c_out (half = t>>7) x 8 px. acc2[2 co-pairs][8 px] f32x2.
// Input smem: sin2[4ci][34 rows][36 u64] of (v,v) pairs; position c stored at
// col c + (c>=16 ? 2 : 0). Two passes over ci (0-3, then 4-7).
// ---------------------------------------------------------------------------
__global__ __launch_bounds__(256, 4) void hyper_conv_kernel(
    const float* __restrict__ x,       // [16][8][512][512]
    float* __restrict__ out)           // [16][8][512][512]
{
    __shared__ unsigned long long sin2[4 * 34 * 36];          // 38.25 KB
    __shared__ __align__(16) float wsm[72][8];                // 2.25 KB

    const int n  = blockIdx.x;
    const int t  = threadIdx.x;
    const int b  = n >> 8;
    const int fy = (n >> 4) & 15;
    const int fx = n & 15;

    // stage weights once: g_wpp[n][co*72 + kidx] -> wsm[kidx][co]
    const float* wpp_n = g_wpp + (size_t)n * 576;
    for (int i = t; i < 576; i += 256) {
        int co   = i / 72;
        int kidx = i - co * 72;
        wsm[kidx][co] = wpp_n[i];
    }

    const float* xb  = x + (size_t)b * (8 * 512 * 512);
    const int row0 = fy * 32 - 1;
    const int col0 = fx * 32 - 1;

    const int cohalf = t >> 7;          // 0: co 0-3, 1: co 4-7
    const int tt  = t & 127;
    const int py  = tt >> 2;            // 0..31
    const int px0 = (tt & 3) << 3;      // 0,8,16,24

    // per-thread read bases (gap-aware, uniform arithmetic)
    const int ofsA = px0 + (px0 >= 16 ? 2 : 0);          // positions px0..px0+7
    const int ofsB = px0 + 8 + (px0 + 8 >= 16 ? 2 : 0);  // positions px0+8, +9

    unsigned long long acc2[2][8];
#pragma unroll
    for (int cp = 0; cp < 2; cp++)
#pragma unroll
        for (int p = 0; p < 8; p++) acc2[cp][p] = 0ull;

#pragma unroll 1
    for (int pass = 0; pass < 2; pass++) {
        __syncthreads();   // previous-pass reads done (pass0: weights published)

        // stage 4 ci slices, reflect-padded, duplicated (v,v)
        for (int i = t; i < 4 * 34 * 34; i += 256) {
            int ci4 = i / 1156;
            int rem = i - ci4 * 1156;
            int r   = rem / 34;
            int cl  = rem - r * 34;
            int gr = row0 + r;  gr = gr < 0 ? -gr : (gr > 511 ? 1022 - gr : gr);
            int gc = col0 + cl; gc = gc < 0 ? -gc : (gc > 511 ? 1022 - gc : gc);
            float v = xb[(((pass << 2) + ci4) << 18) + (gr << 9) + gc];
            int idx = (ci4 * 34 + r) * 36 + cl + (cl >= 16 ? 2 : 0);
            *reinterpret_cast<float2*>(&sin2[idx]) = make_float2(v, v);
        }
        __syncthreads();

#pragma unroll 1
        for (int ci4 = 0; ci4 < 4; ci4++) {
            const int ci = (pass << 2) + ci4;
#pragma unroll
            for (int kr = 0; kr < 3; kr++) {
                const unsigned long long* rowb =
                    &sin2[(ci4 * 34 + py + kr) * 36];
                ulonglong2 u0 = *reinterpret_cast<const ulonglong2*>(rowb + ofsA);
                ulonglong2 u1 = *reinterpret_cast<const ulonglong2*>(rowb + ofsA + 2);
                ulonglong2 u2 = *reinterpret_cast<const ulonglong2*>(rowb + ofsA + 4);
                ulonglong2 u3 = *reinterpret_cast<const ulonglong2*>(rowb + ofsA + 6);
                ulonglong2 u4 = *reinterpret_cast<const ulonglong2*>(rowb + ofsB);
                unsigned long long P[10] = {u0.x, u0.y, u1.x, u1.y,
                                            u2.x, u2.y, u3.x, u3.y,
                                            u4.x, u4.y};
                const int kbase = ci * 9 + kr * 3;
#pragma unroll
                for (int kc = 0; kc < 3; kc++) {
                    const ulonglong2 w = *reinterpret_cast<const ulonglong2*>(
                        &wsm[kbase + kc][cohalf * 4]);   // co-pairs (0,1),(2,3)
#pragma unroll
                    for (int p = 0; p < 8; p++) {
                        acc2[0][p] = ffma2(w.x, P[kc + p], acc2[0][p]);
                        acc2[1][p] = ffma2(w.y, P[kc + p], acc2[1][p]);
                    }
                }
            }
        }
    }

    const int gy = (fy << 5) + py;
    const int gx = (fx << 5) + px0;
    const int co_base = b * 8 + cohalf * 4;
#pragma unroll
    for (int cp = 0; cp < 2; cp++) {
        float lo[8], hi[8];
#pragma unroll
        for (int p = 0; p < 8; p++) unpack2(acc2[cp][p], lo[p], hi[p]);
        float* op0 = out + (((size_t)(co_base + 2 * cp))     << 18) + (gy << 9) + gx;
        float* op1 = out + (((size_t)(co_base + 2 * cp + 1)) << 18) + (gy << 9) + gx;
        *reinterpret_cast<float4*>(op0)     = make_float4(lo[0], lo[1], lo[2], lo[3]);
        *reinterpret_cast<float4*>(op0 + 4) = make_float4(lo[4], lo[5], lo[6], lo[7]);
        *reinterpret_cast<float4*>(op1)     = make_float4(hi[0], hi[1], hi[2], hi[3]);
        *reinterpret_cast<float4*>(op1 + 4) = make_float4(hi[4], hi[5], hi[6], hi[7]);
    }
}

// ---------------------------------------------------------------------------
extern "C" void kernel_launch(void* const* d_in, const int* in_sizes, int n_in,
                              void* d_out, int out_size)
{
    (void)in_sizes; (void)n_in; (void)out_size;
    const float* x     = (const float*)d_in[0];   // [16,8,512,512]
    const float* s     = (const float*)d_in[1];   // [16,64,16,16]
    const float* w_s2w = (const float*)d_in[2];   // [576,64]
    float* out = (float*)d_out;                   // [16,8,512,512]

    hyper_weights_kernel<<<dim3(32, 72), 128>>>(w_s2w, s);
    hyper_conv_kernel<<<N_TILES, 256>>>(x, out);
}

// round 10
// speedup vs baseline: 1.4796x; 1.1599x over previous
#include <cuda_runtime.h>

// HyperPatch: b=16, c=8, h=w=512, fh=fw=16, c_out=8, sc=64, K=3, PAD=1
// R8 (3rd submit; infra failures R8/R9): R4 structure (register pack2 +
//     co-pairs f32x2) + software-pipelining room: unroll ci x2,
//     launch_bounds(256,3) (~85 regs), weight LDS hoisted before packs.

#define N_TILES 4096
__device__ float g_wpp[N_TILES * 576];   // scratch: [n][o]

// ---- f32x2 helpers ---------------------------------------------------------
__device__ __forceinline__ unsigned long long ffma2(
    unsigned long long a, unsigned long long b, unsigned long long c)
{
    unsigned long long d;
    asm("fma.rn.f32x2 %0, %1, %2, %3;" : "=l"(d) : "l"(a), "l"(b), "l"(c));
    return d;
}
__device__ __forceinline__ unsigned long long pack2(float x)
{
    unsigned long long d;
    asm("mov.b64 %0, {%1, %1};" : "=l"(d) : "f"(x));
    return d;
}
__device__ __forceinline__ void unpack2(unsigned long long v, float& lo, float& hi)
{
    asm("mov.b64 {%0, %1}, %2;" : "=f"(lo), "=f"(hi) : "l"(v));
}

// ---------------------------------------------------------------------------
// Kernel 1: g_wpp[4096 x 576] = S[4096 x 64] @ w_s2w^T   (proven R1 version)
// ---------------------------------------------------------------------------
__global__ __launch_bounds__(128) void hyper_weights_kernel(
    const float* __restrict__ w_s2w,   // [576][64]
    const float* __restrict__ s_in)    // [16][64][256]
{
    __shared__ float wsm[512];   // 8 rows x 64
    const int t  = threadIdx.x;
    const int o0 = blockIdx.y * 8;

#pragma unroll
    for (int i = 0; i < 4; i++)
        wsm[t + i * 128] = w_s2w[o0 * 64 + t + i * 128];
    __syncthreads();

    const int n    = blockIdx.x * 128 + t;
    const int b    = n >> 8;
    const int fyfx = n & 255;
    const float* sp = s_in + b * (64 * 256) + fyfx;

    float acc[8];
#pragma unroll
    for (int k = 0; k < 8; k++) acc[k] = 0.f;

#pragma unroll 8
    for (int s = 0; s < 64; s++) {
        float a = __ldg(sp + s * 256);
#pragma unroll
        for (int k = 0; k < 8; k++)
            acc[k] = fmaf(wsm[k * 64 + s], a, acc[k]);
    }

    float4* dst = reinterpret_cast<float4*>(g_wpp + (size_t)n * 576 + o0);
    dst[0] = make_float4(acc[0], acc[1], acc[2], acc[3]);
    dst[1] = make_float4(acc[4], acc[5], acc[6], acc[7]);
}

// ---------------------------------------------------------------------------
// Kernel 2: per-tile 3x3 conv. grid = 4096 tiles, 256 threads.
// Thread: 4 c_out (half = t>>7) x 8 px, acc as 2 co-pair x 8 px f32x2.
// smem: input [8ci][34][36] plain f32, weights [kidx=72][co=8].
// ---------------------------------------------------------------------------
__global__ __launch_bounds__(256, 3) void hyper_conv_kernel(
    const float* __restrict__ x,       // [16][8][512][512]
    float* __restrict__ out)           // [16][8][512][512]
{
    __shared__ float sin_s[8][34][36];
    __shared__ __align__(16) float wsm[72][8];

    const int n  = blockIdx.x;
    const int t  = threadIdx.x;
    const int b  = n >> 8;
    const int fy = (n >> 4) & 15;
    const int fx = n & 15;

    // stage weights: g_wpp[n][co*72 + kidx] -> wsm[kidx][co]
    const float* wpp_n = g_wpp + (size_t)n * 576;
    for (int i = t; i < 576; i += 256) {
        int co   = i / 72;
        int kidx = i - co * 72;
        wsm[kidx][co] = wpp_n[i];
    }

    // stage 34x34x8 reflect-padded input window
    const float* xb  = x + (size_t)b * (8 * 512 * 512);
    const int row0 = fy * 32 - 1;
    const int col0 = fx * 32 - 1;
    for (int i = t; i < 8 * 34 * 34; i += 256) {
        int ci  = i / 1156;
        int rem = i - ci * 1156;
        int r   = rem / 34;
        int cl  = rem - r * 34;
        int gr = row0 + r;  gr = gr < 0 ? -gr : (gr > 511 ? 1022 - gr : gr);
        int gc = col0 + cl; gc = gc < 0 ? -gc : (gc > 511 ? 1022 - gc : gc);
        sin_s[ci][r][cl] = xb[(ci << 18) + (gr << 9) + gc];
    }
    __syncthreads();

    const int cohalf = t >> 7;          // 0: co 0-3, 1: co 4-7
    const int tt  = t & 127;
    const int py  = tt >> 2;            // 0..31
    const int px0 = (tt & 3) << 3;      // 0,8,16,24

    unsigned long long acc2[2][8];      // [co-pair within half][pixel]
#pragma unroll
    for (int cp = 0; cp < 2; cp++)
#pragma unroll
        for (int p = 0; p < 8; p++) acc2[cp][p] = 0ull;

#pragma unroll 2
    for (int ci = 0; ci < 8; ci++) {
#pragma unroll
        for (int kr = 0; kr < 3; kr++) {
            // hoist weight loads for all 3 kc (broadcast LDS.128)
            const int kbase = ci * 9 + kr * 3;
            ulonglong2 w0 = *reinterpret_cast<const ulonglong2*>(
                &wsm[kbase][cohalf * 4]);
            ulonglong2 w1 = *reinterpret_cast<const ulonglong2*>(
                &wsm[kbase + 1][cohalf * 4]);
            ulonglong2 w2 = *reinterpret_cast<const ulonglong2*>(
                &wsm[kbase + 2][cohalf * 4]);

            const float* rowp = &sin_s[ci][py + kr][px0];
            float4 A  = *reinterpret_cast<const float4*>(rowp);
            float4 B  = *reinterpret_cast<const float4*>(rowp + 4);
            float2 Cc = *reinterpret_cast<const float2*>(rowp + 8);
            unsigned long long in2[10];
            in2[0] = pack2(A.x);  in2[1] = pack2(A.y);
            in2[2] = pack2(A.z);  in2[3] = pack2(A.w);
            in2[4] = pack2(B.x);  in2[5] = pack2(B.y);
            in2[6] = pack2(B.z);  in2[7] = pack2(B.w);
            in2[8] = pack2(Cc.x); in2[9] = pack2(Cc.y);

#pragma unroll
            for (int p = 0; p < 8; p++) {
                acc2[0][p] = ffma2(w0.x, in2[p],     acc2[0][p]);
                acc2[1][p] = ffma2(w0.y, in2[p],     acc2[1][p]);
                acc2[0][p] = ffma2(w1.x, in2[p + 1], acc2[0][p]);
                acc2[1][p] = ffma2(w1.y, in2[p + 1], acc2[1][p]);
                acc2[0][p] = ffma2(w2.x, in2[p + 2], acc2[0][p]);
                acc2[1][p] = ffma2(w2.y, in2[p + 2], acc2[1][p]);
            }
        }
    }

    const int gy = (fy << 5) + py;
    const int gx = (fx << 5) + px0;
    const int co_base = b * 8 + cohalf * 4;
#pragma unroll
    for (int cp = 0; cp < 2; cp++) {
        float lo[8], hi[8];
#pragma unroll
        for (int p = 0; p < 8; p++) unpack2(acc2[cp][p], lo[p], hi[p]);
        float* op0 = out + (((size_t)(co_base + 2 * cp))     << 18) + (gy << 9) + gx;
        float* op1 = out + (((size_t)(co_base + 2 * cp + 1)) << 18) + (gy << 9) + gx;
        *reinterpret_cast<float4*>(op0)     = make_float4(lo[0], lo[1], lo[2], lo[3]);
        *reinterpret_cast<float4*>(op0 + 4) = make_float4(lo[4], lo[5], lo[6], lo[7]);
        *reinterpret_cast<float4*>(op1)     = make_float4(hi[0], hi[1], hi[2], hi[3]);
        *reinterpret_cast<float4*>(op1 + 4) = make_float4(hi[4], hi[5], hi[6], hi[7]);
    }
}

// ---------------------------------------------------------------------------
extern "C" void kernel_launch(void* const* d_in, const int* in_sizes, int n_in,
                              void* d_out, int out_size)
{
    (void)in_sizes; (void)n_in; (void)out_size;
    const float* x     = (const float*)d_in[0];   // [16,8,512,512]
    const float* s     = (const float*)d_in[1];   // [16,64,16,16]
    const float* w_s2w = (const float*)d_in[2];   // [576,64]
    float* out = (float*)d_out;                   // [16,8,512,512]

    hyper_weights_kernel<<<dim3(32, 72), 128>>>(w_s2w, s);
    hyper_conv_kernel<<<N_TILES, 256>>>(x, out);
}